// round 12
// baseline (speedup 1.0000x reference)
#include <cuda_runtime.h>
#include <cuda_fp16.h>
#include <math.h>
#include <stdint.h>

// Problem constants (fixed by setup_inputs)
#define B_   64
#define L_   680
#define C_   1024
#define NSEG 10

__constant__ int       c_start[NSEG] = {0,1,5,14,30,55,91,155,255,424};
__constant__ int       c_len[NSEG]   = {1,4,9,16,25,36,64,100,169,256};
__constant__ long long c_base[NSEG]  = {0LL,8192LL,73728LL,294912LL,819200LL,
                                        1843200LL,3612672LL,7282688LL,13836288LL,26296320LL};
// Tile prefix tables for BM=256 tiles:
//   mtiles_i = ceil(64*len_i/256) = {1,1,3,4,7,9,16,25,43,64}
__constant__ int c_stp[NSEG + 1] = {0,1,3,12,28,63,117,229,429,816,1456};
__constant__ int c_atp[NSEG + 1] = {0,8,16,40,72,128,200,328,528,872,1384};

// Static device scratch
__device__ __align__(16) __half g_xh  [44564480]; // x as half
__device__ __align__(16) __half g_memh[1310720];  // mem as half
__device__ __align__(16) __half g_Q   [44564480]; // Q (half)
__device__ __align__(16) __half g_KVh [2621440];  // [1280][2048] K|V (half)
__device__ __align__(16) __half g_Vt  [1310720];  // [1024][1280] V^T (half)
__device__ __align__(16) float  g_S   [47267840]; // scores (f32, segment-packed)
__device__ __align__(16) __half g_P   [47267840]; // attn probs (half, same packing)
__device__ __align__(16) __half g_MC  [44564480]; // mem_combined (half)
__device__ __align__(16) __half g_mid [5570560];  // [43520][128] (half)
__device__ __align__(16) __half g_WqT [1048576];  // Wq^T [1024][1024]
__device__ __align__(16) __half g_wkvT[2097152];  // [2048][1024] Wk^T|Wv^T
__device__ __align__(16) __half g_w12T[131072];   // [128][1024] wk1^T|wv1^T
__device__ __align__(16) __half g_w34T[131072];   // wk2^T [1024][64] @0 | wv2^T @65536
__device__ float  g_b12 [128];                    // bk1|bv1 (f32)

// Smem: per stage, A 256 rows x 144B = 36864, B 128 rows x 144B = 18432
#define ROW_BYTES    144
#define A_STAGE_B    36864
#define B_STAGE_B    18432
#define STAGE_B      55296
#define NSTAGE       3
#define SMEM_BYTES   (NSTAGE * STAGE_B)   // 165888

__device__ __forceinline__ void cp16(uint32_t dst, const void* src, int szbytes) {
    asm volatile("cp.async.cg.shared.global [%0], [%1], 16, %2;"
                 :: "r"(dst), "l"(src), "r"(szbytes));
}
__device__ __forceinline__ void cp_commit() { asm volatile("cp.async.commit_group;"); }
__device__ __forceinline__ void cp_wait1()  { asm volatile("cp.async.wait_group 1;"); }
__device__ __forceinline__ void cp_wait0()  { asm volatile("cp.async.wait_group 0;"); }

__device__ __forceinline__ void ldmx4(uint32_t a, uint32_t& r0, uint32_t& r1,
                                      uint32_t& r2, uint32_t& r3) {
    asm volatile("ldmatrix.sync.aligned.m8n8.x4.shared.b16 {%0,%1,%2,%3}, [%4];"
                 : "=r"(r0), "=r"(r1), "=r"(r2), "=r"(r3) : "r"(a));
}

// ---------------------------------------------------------------------------
// FP16 NT GEMM core: one 256x128 C-tile at (m0, n0).
//   A: [M,K] half (lda); alen>0 => row remap (m/alen)*680+astart+(m%alen)
//   B: [N,K] half (ldb); n0+128 <= N (all N multiples of 128)
//   C: [M,N]; clen>0 => row remap; half or f32 output
// K % 64 == 0. M edge zero-filled (cp.async src-size 0) + store-guarded.
// 256 threads, 8 warps, 64x64 warp tile, m16n8k16 f16 mma, f32 accum.
// 3-stage cp.async ring, one __syncthreads per K-chunk; fragment loads via
// ldmatrix.x4 (conflict-free at 144B row stride: banks 4l mod 32).
// ---------------------------------------------------------------------------
__device__ __forceinline__ void hcore(
    const __half* __restrict__ A, int lda,
    const __half* __restrict__ B, int ldb,
    void* __restrict__ C, int ldc,
    int M, int K,
    int alen, int astart, int clen, int cstart,
    const float* __restrict__ bias,
    const float* __restrict__ gate_logit,
    int m0, int n0, bool outHalf)
{
    extern __shared__ char smraw[];
    const uint32_t smb = (uint32_t)__cvta_generic_to_shared(smraw);

    const int tid  = threadIdx.x;
    const int lane = tid & 31;
    const int w    = tid >> 5;
    const int wm   = (w & 3) * 64;
    const int wn   = (w >> 2) * 64;
    const int g    = lane >> 2;
    const int t4   = lane & 3;

    float acc[4][8][4];
    #pragma unroll
    for (int i = 0; i < 4; i++)
        #pragma unroll
        for (int j = 0; j < 8; j++)
            #pragma unroll
            for (int k = 0; k < 4; k++) acc[i][j][k] = 0.f;

    // ---- A: thread owns row m0+tid; 64 halves (128B) per chunk = 8 cp16 ----
    const int am    = m0 + tid;
    const bool amOK = am < M;
    const int amc   = amOK ? am : 0;
    long long arow = (alen > 0)
        ? (long long)(amc / alen) * L_ + astart + (amc % alen)
        : (long long)amc;
    const __half* Aptr = A + arow * (long long)lda;
    const int a_sz = amOK ? 16 : 0;
    const uint32_t a_dst = smb + (uint32_t)tid * ROW_BYTES;

    // ---- B: 128 rows; thread covers row tid>>1, half-row part (tid&1) ----
    const int brow = tid >> 1;
    const int bp   = tid & 1;
    const __half* Bptr = B + (long long)(n0 + brow) * ldb + bp * 32;
    const uint32_t b_dst = smb + A_STAGE_B + (uint32_t)brow * ROW_BYTES + (uint32_t)bp * 64u;

    // ---- ldmatrix lane-dependent base offsets (stage-independent) ----
    // A (per mi): lanes 0-7 m-lo rows @k, 8-15 m-hi @k, 16-23 m-lo @k+16B, 24-31 m-hi @k+16B
    uint32_t a_off[4], b_off[4];
    #pragma unroll
    for (int mi = 0; mi < 4; mi++)
        a_off[mi] = (uint32_t)((wm + mi * 16 + (lane & 15)) * ROW_BYTES + (lane >> 4) * 16);
    // B (per ni-pair): lanes 0-7 n-lo @k, 8-15 n-lo @k+16B, 16-23 n-hi @k, 24-31 n-hi @k+16B
    #pragma unroll
    for (int n2 = 0; n2 < 4; n2++)
        b_off[n2] = (uint32_t)((wn + n2 * 16 + (lane & 7) + ((lane >> 4) << 3)) * ROW_BYTES
                               + ((lane >> 3) & 1) * 16);

    auto issue = [&](int s, int chunk) {
        int k0 = chunk * 64;
        uint32_t soff = (uint32_t)s * STAGE_B;
        const __half* ap = Aptr + k0;
        uint32_t ad = a_dst + soff;
        #pragma unroll
        for (int j = 0; j < 8; j++)
            cp16(ad + j * 16, ap + j * 8, a_sz);
        const __half* bpp = Bptr + k0;
        uint32_t bd = b_dst + soff;
        #pragma unroll
        for (int j = 0; j < 4; j++)
            cp16(bd + j * 16, bpp + j * 8, 16);
        cp_commit();
    };

    auto compute = [&](int s) {
        const uint32_t Ab = smb + (uint32_t)s * STAGE_B;
        const uint32_t Bb = Ab + A_STAGE_B;
        #pragma unroll
        for (int kb = 0; kb < 4; kb++) {
            const uint32_t kB = (uint32_t)kb * 32;   // 16 halves = 32 bytes
            uint32_t af[4][4], br[4][4];
            #pragma unroll
            for (int mi = 0; mi < 4; mi++)
                ldmx4(Ab + a_off[mi] + kB, af[mi][0], af[mi][1], af[mi][2], af[mi][3]);
            #pragma unroll
            for (int n2 = 0; n2 < 4; n2++)
                ldmx4(Bb + b_off[n2] + kB, br[n2][0], br[n2][1], br[n2][2], br[n2][3]);
            #pragma unroll
            for (int mi = 0; mi < 4; mi++)
                #pragma unroll
                for (int n2 = 0; n2 < 4; n2++) {
                    asm volatile(
                        "mma.sync.aligned.m16n8k16.row.col.f32.f16.f16.f32 "
                        "{%0,%1,%2,%3},{%4,%5,%6,%7},{%8,%9},{%0,%1,%2,%3};"
                        : "+f"(acc[mi][n2 * 2][0]), "+f"(acc[mi][n2 * 2][1]),
                          "+f"(acc[mi][n2 * 2][2]), "+f"(acc[mi][n2 * 2][3])
                        : "r"(af[mi][0]), "r"(af[mi][1]),
                          "r"(af[mi][2]), "r"(af[mi][3]),
                          "r"(br[n2][0]), "r"(br[n2][1]));
                    asm volatile(
                        "mma.sync.aligned.m16n8k16.row.col.f32.f16.f16.f32 "
                        "{%0,%1,%2,%3},{%4,%5,%6,%7},{%8,%9},{%0,%1,%2,%3};"
                        : "+f"(acc[mi][n2 * 2 + 1][0]), "+f"(acc[mi][n2 * 2 + 1][1]),
                          "+f"(acc[mi][n2 * 2 + 1][2]), "+f"(acc[mi][n2 * 2 + 1][3])
                        : "r"(af[mi][0]), "r"(af[mi][1]),
                          "r"(af[mi][2]), "r"(af[mi][3]),
                          "r"(br[n2][2]), "r"(br[n2][3]));
                }
        }
    };

    // ---- 3-stage ring, single sync per chunk (ordering proven in R9) ----
    const int T = K >> 6;
    issue(0, 0);
    if (T > 1) issue(1, 1);
    for (int i = 0; i < T; i++) {
        if (i + 2 < T) cp_wait1(); else cp_wait0();
        __syncthreads();
        if (i + 2 < T) issue((i + 2) % NSTAGE, i + 2);
        compute(i % NSTAGE);
    }

    // ---- epilogue ----
    float gate = 1.0f;
    if (gate_logit) gate = 1.0f / (1.0f + expf(-(*gate_logit)));

    #pragma unroll
    for (int mi = 0; mi < 4; mi++) {
        #pragma unroll
        for (int rr = 0; rr < 2; rr++) {
            int m = m0 + wm + mi * 16 + g + rr * 8;
            if (m >= M) continue;
            long long crow = (clen > 0)
                ? (long long)(m / clen) * L_ + cstart + (m % clen)
                : (long long)m;
            #pragma unroll
            for (int ni = 0; ni < 8; ni++) {
                int n = n0 + wn + ni * 8 + t4 * 2;
                float v0 = acc[mi][ni][rr * 2 + 0];
                float v1 = acc[mi][ni][rr * 2 + 1];
                if (bias) { v0 += bias[n]; v1 += bias[n + 1]; }
                v0 *= gate; v1 *= gate;
                if (outHalf) {
                    __half* cp = (__half*)C + crow * (long long)ldc + n;
                    *(__half2*)cp = __floats2half2_rn(v0, v1);
                } else {
                    float* cp = (float*)C + crow * (long long)ldc + n;
                    cp[0] = v0; cp[1] = v1;
                }
            }
        }
    }
}

// ---------------------------------------------------------------------------
__global__ void hgemm(const __half* __restrict__ A, int lda,
                      const __half* __restrict__ B, int ldb,
                      void* __restrict__ C, int ldc,
                      int M, int K,
                      const float* __restrict__ bias,
                      const float* __restrict__ gate_logit,
                      int outHalf)
{
    hcore(A, lda, B, ldb, C, ldc, M, K, 0, 0, 0, 0,
          bias, gate_logit, blockIdx.y * 256, blockIdx.x * 128, outHalf != 0);
}

// Fused scores: all 10 segments (1456 tiles). A=Q remapped; C = f32 scores.
__global__ void scores_kernel()
{
    int t = blockIdx.x;
    int seg = 0;
    #pragma unroll
    for (int i = 1; i < NSEG; i++) if (t >= c_stp[i]) seg = i;
    int local = t - c_stp[seg];
    int nt = seg + 1;
    int tm = local / nt;
    int tn = local - tm * nt;
    int len = c_len[seg], start = c_start[seg];
    int Nseg = 128 * nt, Mseg = 64 * len;
    hcore(g_Q, C_, g_KVh, 2048, g_S + c_base[seg], Nseg,
          Mseg, C_, len, start, 0, 0, nullptr, nullptr,
          tm * 256, tn * 128, false);
}

// Fused attn@V: all 10 segments (1384 tiles). A = probs (half); C = MC (half).
__global__ void attnv_kernel()
{
    int t = blockIdx.x;
    int seg = 0;
    #pragma unroll
    for (int i = 1; i < NSEG; i++) if (t >= c_atp[i]) seg = i;
    int local = t - c_atp[seg];
    int tm = local >> 3;
    int tn = local & 7;
    int len = c_len[seg], start = c_start[seg];
    int Nseg = 128 * (seg + 1), Mseg = 64 * len;
    hcore(g_P + c_base[seg], Nseg, g_Vt, 1280, g_MC, C_,
          Mseg, Nseg, 0, 0, len, start, nullptr, nullptr,
          tm * 256, tn * 128, true);
}

// ---------------------------------------------------------------------------
// Row softmax: read f32 scores (g_S), write half probs (g_P).
// scale = (1/32)/clip(exp(log_temp), 0.05, 1)
// ---------------------------------------------------------------------------
__global__ void softmax_kernel(const float* __restrict__ log_temp)
{
    int row = blockIdx.x;
    int b = row / L_;
    int l = row - b * L_;

    int seg = 0;
    #pragma unroll
    for (int s2 = 1; s2 < NSEG; s2++)
        if (l >= c_start[s2]) seg = s2;

    const int n   = 128 * (seg + 1);
    const int len = c_len[seg];
    long long off = c_base[seg] + ((long long)b * len + (l - c_start[seg])) * (long long)n;
    const float* p = g_S + off;
    __half* q = g_P + off;

    float t = expf(*log_temp);
    t = fminf(fmaxf(t, 0.05f), 1.0f);
    const float scale = (1.0f / 32.0f) / t;

    __shared__ float sh[8];
    const int lane = threadIdx.x & 31;
    const int w    = threadIdx.x >> 5;

    float m = -1e30f;
    for (int j = threadIdx.x; j < n; j += 256) m = fmaxf(m, p[j] * scale);
    #pragma unroll
    for (int o = 16; o; o >>= 1) m = fmaxf(m, __shfl_xor_sync(0xffffffffu, m, o));
    if (lane == 0) sh[w] = m;
    __syncthreads();
    m = sh[lane & 7];
    #pragma unroll
    for (int o = 4; o; o >>= 1) m = fmaxf(m, __shfl_xor_sync(0xffffffffu, m, o));

    float sum = 0.f;
    for (int j = threadIdx.x; j < n; j += 256)
        sum += expf(p[j] * scale - m);
    #pragma unroll
    for (int o = 16; o; o >>= 1) sum += __shfl_xor_sync(0xffffffffu, sum, o);
    __syncthreads();
    if (lane == 0) sh[w] = sum;
    __syncthreads();
    sum = sh[lane & 7];
    #pragma unroll
    for (int o = 4; o; o >>= 1) sum += __shfl_xor_sync(0xffffffffu, sum, o);

    const float inv = 1.0f / sum;
    for (int j = threadIdx.x; j < n; j += 256)
        q[j] = __float2half_rn(expf(p[j] * scale - m) * inv);
}

// ---------------------------------------------------------------------------
// Utility kernels
// ---------------------------------------------------------------------------
__global__ void f2h_kernel(const float* __restrict__ src,
                           __half* __restrict__ dst, int n4)
{
    int i = blockIdx.x * 256 + threadIdx.x;
    if (i < n4) {
        float4 v = ((const float4*)src)[i];
        ((__half2*)dst)[i * 2 + 0] = __floats2half2_rn(v.x, v.y);
        ((__half2*)dst)[i * 2 + 1] = __floats2half2_rn(v.z, v.w);
    }
}

// dst[c*dld + r] = (half)src[r*sld + c]
__global__ void transpose_f2h(const float* __restrict__ src, int sld,
                              __half* __restrict__ dst, int dld,
                              int R, int Cc)
{
    __shared__ float t[32][33];
    int bx = blockIdx.x * 32, by = blockIdx.y * 32;
    int x = bx + threadIdx.x, y = by + threadIdx.y;
    if (x < Cc && y < R) t[threadIdx.y][threadIdx.x] = src[(long long)y * sld + x];
    __syncthreads();
    int xo = by + threadIdx.x, yo = bx + threadIdx.y;
    if (xo < R && yo < Cc)
        dst[(long long)yo * dld + xo] = __float2half_rn(t[threadIdx.x][threadIdx.y]);
}

// dst[c*dld + r] = src[r*sld + c] (half -> half)
__global__ void transpose_h2h(const __half* __restrict__ src, int sld,
                              __half* __restrict__ dst, int dld,
                              int R, int Cc)
{
    __shared__ __half t[32][33];
    int bx = blockIdx.x * 32, by = blockIdx.y * 32;
    int x = bx + threadIdx.x, y = by + threadIdx.y;
    if (x < Cc && y < R) t[threadIdx.y][threadIdx.x] = src[(long long)y * sld + x];
    __syncthreads();
    int xo = by + threadIdx.x, yo = bx + threadIdx.y;
    if (xo < R && yo < Cc)
        dst[(long long)yo * dld + xo] = t[threadIdx.x][threadIdx.y];
}

__global__ void bias_pack_kernel(const float* __restrict__ bk1,
                                 const float* __restrict__ bv1)
{
    int i = threadIdx.x;
    if (i < 64) { g_b12[i] = bk1[i]; g_b12[64 + i] = bv1[i]; }
}

__global__ void tail_kernel(float* out, long long off)
{
    if (threadIdx.x < 2) out[off + threadIdx.x] = 0.f;
}

// ---------------------------------------------------------------------------
extern "C" void kernel_launch(void* const* d_in, const int* in_sizes, int n_in,
                              void* d_out, int out_size)
{
    const float* x   = (const float*)d_in[0];
    const float* mem = (const float*)d_in[1];
    const float* Wq  = (const float*)d_in[2];
    const float* Wk  = (const float*)d_in[3];
    const float* Wv  = (const float*)d_in[4];
    const float* wk1 = (const float*)d_in[5];
    const float* bk1 = (const float*)d_in[6];
    const float* wk2 = (const float*)d_in[7];
    const float* bk2 = (const float*)d_in[8];
    const float* wv1 = (const float*)d_in[9];
    const float* bv1 = (const float*)d_in[10];
    const float* wv2 = (const float*)d_in[11];
    const float* bv2 = (const float*)d_in[12];
    const float* gk  = (const float*)d_in[13];
    const float* gv  = (const float*)d_in[14];
    const float* lt  = (const float*)d_in[15];
    float* out = (float*)d_out;

    __half *xh, *memh, *Q, *KVh, *Vt, *P, *MC, *mid, *WqT, *wkvT, *w12T, *w34T;
    float *S, *b12;
    cudaGetSymbolAddress((void**)&xh,   g_xh);
    cudaGetSymbolAddress((void**)&memh, g_memh);
    cudaGetSymbolAddress((void**)&Q,    g_Q);
    cudaGetSymbolAddress((void**)&KVh,  g_KVh);
    cudaGetSymbolAddress((void**)&Vt,   g_Vt);
    cudaGetSymbolAddress((void**)&S,    g_S);
    cudaGetSymbolAddress((void**)&P,    g_P);
    cudaGetSymbolAddress((void**)&MC,   g_MC);
    cudaGetSymbolAddress((void**)&mid,  g_mid);
    cudaGetSymbolAddress((void**)&WqT,  g_WqT);
    cudaGetSymbolAddress((void**)&wkvT, g_wkvT);
    cudaGetSymbolAddress((void**)&w12T, g_w12T);
    cudaGetSymbolAddress((void**)&w34T, g_w34T);
    cudaGetSymbolAddress((void**)&b12,  g_b12);

    cudaFuncSetAttribute(hgemm,         cudaFuncAttributeMaxDynamicSharedMemorySize, SMEM_BYTES);
    cudaFuncSetAttribute(scores_kernel, cudaFuncAttributeMaxDynamicSharedMemorySize, SMEM_BYTES);
    cudaFuncSetAttribute(attnv_kernel,  cudaFuncAttributeMaxDynamicSharedMemorySize, SMEM_BYTES);

    dim3 tb(32, 32);

    // 0) convert / transpose inputs & weights to half
    f2h_kernel<<<43520, 256>>>(x,   xh,   (B_ * L_ * C_) / 4);
    f2h_kernel<<<1280,  256>>>(mem, memh, (NSEG * 128 * C_) / 4);
    transpose_f2h<<<dim3(32, 32), tb>>>(Wq,  C_, WqT,            C_, C_, C_);
    transpose_f2h<<<dim3(32, 32), tb>>>(Wk,  C_, wkvT,           C_, C_, C_);
    transpose_f2h<<<dim3(32, 32), tb>>>(Wv,  C_, wkvT + 1048576, C_, C_, C_);
    transpose_f2h<<<dim3(2,  32), tb>>>(wk1, 64, w12T,           C_, C_, 64);
    transpose_f2h<<<dim3(2,  32), tb>>>(wv1, 64, w12T + 65536,   C_, C_, 64);
    transpose_f2h<<<dim3(32, 2),  tb>>>(wk2, C_, w34T,           64, 64, C_);
    transpose_f2h<<<dim3(32, 2),  tb>>>(wv2, C_, w34T + 65536,   64, 64, C_);
    bias_pack_kernel<<<1, 64>>>(bk1, bv1);

    // 1) projections: Q = x@Wq (half out); KV = mem@[Wk|Wv] (half out)
    hgemm<<<dim3(8, 170), 256, SMEM_BYTES>>>(xh,   C_, WqT,  C_, Q,   C_,
                                             B_ * L_,    C_, nullptr, nullptr, 1);
    hgemm<<<dim3(16, 5),  256, SMEM_BYTES>>>(memh, C_, wkvT, C_, KVh, 2048,
                                             NSEG * 128, C_, nullptr, nullptr, 1);

    // 1b) V^T (half): Vt[c][t] = KV[t][1024+c]
    transpose_h2h<<<dim3(32, 40), tb>>>(KVh + 1024, 2048, Vt, 1280, NSEG * 128, C_);

    // 2) all score GEMMs (f32 scores)
    scores_kernel<<<1456, 256, SMEM_BYTES>>>();

    // 3) softmax: f32 scores -> half probs
    softmax_kernel<<<B_ * L_, 256>>>(lt);

    // 4) all attn @ V GEMMs (half MC)
    attnv_kernel<<<1384, 256, SMEM_BYTES>>>();

    // 5) mid = MC @ [wk1|wv1] + [bk1|bv1] (half out)
    hgemm<<<dim3(1, 170), 256, SMEM_BYTES>>>(MC, C_, w12T, C_, mid, 128,
                                             B_ * L_, C_, b12, nullptr, 1);

    // 6) up-projections with bias+gate epilogue (f32 final outputs)
    hgemm<<<dim3(8, 170), 256, SMEM_BYTES>>>(mid,      128, w34T,         64,
                                             out, C_, B_ * L_, 64, bk2, gk, 0);
    hgemm<<<dim3(8, 170), 256, SMEM_BYTES>>>(mid + 64, 128, w34T + 65536, 64,
                                             out + (long long)B_ * L_ * C_, C_,
                                             B_ * L_, 64, bv2, gv, 0);

    // 7) trailing two scalar zeros
    tail_kernel<<<1, 32>>>(out, 2LL * B_ * L_ * C_);
}

// round 14
// speedup vs baseline: 1.4410x; 1.4410x over previous
#include <cuda_runtime.h>
#include <cuda_fp16.h>
#include <math.h>
#include <stdint.h>

// Problem constants (fixed by setup_inputs)
#define B_   64
#define L_   680
#define C_   1024
#define NSEG 10

__constant__ int       c_start[NSEG] = {0,1,5,14,30,55,91,155,255,424};
__constant__ int       c_len[NSEG]   = {1,4,9,16,25,36,64,100,169,256};
__constant__ long long c_base[NSEG]  = {0LL,8192LL,73728LL,294912LL,819200LL,
                                        1843200LL,3612672LL,7282688LL,13836288LL,26296320LL};
// Tile prefix tables for BM=256 tiles:
//   mtiles_i = ceil(64*len_i/256) = {1,1,3,4,7,9,16,25,43,64}
__constant__ int c_stp[NSEG + 1] = {0,1,3,12,28,63,117,229,429,816,1456};
__constant__ int c_atp[NSEG + 1] = {0,8,16,40,72,128,200,328,528,872,1384};

// Static device scratch
__device__ __align__(16) __half g_xh  [44564480]; // x as half
__device__ __align__(16) __half g_memh[1310720];  // mem as half
__device__ __align__(16) __half g_Q   [44564480]; // Q (half)
__device__ __align__(16) __half g_KVh [2621440];  // [1280][2048] K|V (half)
__device__ __align__(16) __half g_Vt  [1310720];  // [1024][1280] V^T (half)
__device__ __align__(16) float  g_S   [47267840]; // scores (f32, segment-packed)
__device__ __align__(16) __half g_P   [47267840]; // attn probs (half, same packing)
__device__ __align__(16) __half g_MC  [44564480]; // mem_combined (half)
__device__ __align__(16) __half g_mid [5570560];  // [43520][128] (half)
__device__ __align__(16) __half g_WqT [1048576];  // Wq^T [1024][1024]
__device__ __align__(16) __half g_wkvT[2097152];  // [2048][1024] Wk^T|Wv^T
__device__ __align__(16) __half g_w12T[131072];   // [128][1024] wk1^T|wv1^T
__device__ __align__(16) __half g_w34p[262144];   // [2048][128] zero-padded wk2^T|wv2^T
__device__ float  g_b12 [128];                    // bk1|bv1 (f32)
__device__ float  g_b34 [2048];                   // bk2|bv2 (f32)

// Smem: per stage, A 256 rows x 144B = 36864, B 128 rows x 144B = 18432
#define ROW_BYTES    144
#define A_STAGE_B    36864
#define B_STAGE_B    18432
#define STAGE_B      55296
#define NSTAGE       3
#define SMEM_BYTES   (NSTAGE * STAGE_B)   // 165888

#define OUT_HALF_STRIDE 44564480LL

__device__ __forceinline__ void cp16(uint32_t dst, const void* src, int szbytes) {
    asm volatile("cp.async.cg.shared.global [%0], [%1], 16, %2;"
                 :: "r"(dst), "l"(src), "r"(szbytes));
}
__device__ __forceinline__ void cp_commit() { asm volatile("cp.async.commit_group;"); }
__device__ __forceinline__ void cp_wait1()  { asm volatile("cp.async.wait_group 1;"); }
__device__ __forceinline__ void cp_wait0()  { asm volatile("cp.async.wait_group 0;"); }

// ---------------------------------------------------------------------------
// FP16 NT GEMM core (R11-proven): one 256x128 C-tile at (m0, n0).
//   A: [M,K] half (lda); alen>0 => row remap (m/alen)*680+astart+(m%alen)
//   B: [N,K] half (ldb); n0+128 <= N (all N multiples of 128)
//   C: [M,N]; clen>0 => row remap; half or f32 output
//   dualOut: C is the fp32 out buffer split at n=1024 (mem_k | mem_v),
//            gate = sigmoid(g1) for n<1024, sigmoid(g2) otherwise.
// K % 64 == 0. M edge zero-filled + store-guarded.
// 256 threads, 8 warps, 64x64 warp tile, m16n8k16 f16 mma, f32 accum.
// 3-stage cp.async ring, one __syncthreads per K-chunk, scalar fragment LDS.
// ---------------------------------------------------------------------------
__device__ __forceinline__ void hcore(
    const __half* __restrict__ A, int lda,
    const __half* __restrict__ B, int ldb,
    void* __restrict__ C, int ldc,
    int M, int K,
    int alen, int astart, int clen, int cstart,
    const float* __restrict__ bias,
    const float* __restrict__ gate_logit,
    const float* __restrict__ gate_logit2,
    int m0, int n0, bool outHalf, bool dualOut)
{
    extern __shared__ char smraw[];
    const uint32_t smb = (uint32_t)__cvta_generic_to_shared(smraw);

    const int tid  = threadIdx.x;
    const int lane = tid & 31;
    const int w    = tid >> 5;
    const int wm   = (w & 3) * 64;
    const int wn   = (w >> 2) * 64;
    const int g    = lane >> 2;
    const int t4   = lane & 3;

    float acc[4][8][4];
    #pragma unroll
    for (int i = 0; i < 4; i++)
        #pragma unroll
        for (int j = 0; j < 8; j++)
            #pragma unroll
            for (int k = 0; k < 4; k++) acc[i][j][k] = 0.f;

    // ---- A: thread owns row m0+tid; 64 halves (128B) per chunk = 8 cp16 ----
    const int am    = m0 + tid;
    const bool amOK = am < M;
    const int amc   = amOK ? am : 0;
    long long arow = (alen > 0)
        ? (long long)(amc / alen) * L_ + astart + (amc % alen)
        : (long long)amc;
    const __half* Aptr = A + arow * (long long)lda;
    const int a_sz = amOK ? 16 : 0;
    const uint32_t a_dst = smb + (uint32_t)tid * ROW_BYTES;

    // ---- B: 128 rows; thread covers row tid>>1, half-row part (tid&1) ----
    const int brow = tid >> 1;
    const int bp   = tid & 1;
    const __half* Bptr = B + (long long)(n0 + brow) * ldb + bp * 32;
    const uint32_t b_dst = smb + A_STAGE_B + (uint32_t)brow * ROW_BYTES + (uint32_t)bp * 64u;

    auto issue = [&](int s, int chunk) {
        int k0 = chunk * 64;
        uint32_t soff = (uint32_t)s * STAGE_B;
        const __half* ap = Aptr + k0;
        uint32_t ad = a_dst + soff;
        #pragma unroll
        for (int j = 0; j < 8; j++)
            cp16(ad + j * 16, ap + j * 8, a_sz);
        const __half* bpp = Bptr + k0;
        uint32_t bd = b_dst + soff;
        #pragma unroll
        for (int j = 0; j < 4; j++)
            cp16(bd + j * 16, bpp + j * 8, 16);
        cp_commit();
    };

    auto compute = [&](int s) {
        const char* As = smraw + s * STAGE_B;
        const char* Bs = smraw + s * STAGE_B + A_STAGE_B;
        #pragma unroll
        for (int kb = 0; kb < 4; kb++) {
            const int kB = kb * 32;     // 16 halves = 32 bytes per k-step
            uint32_t af[4][4], bf[8][2];
            #pragma unroll
            for (int mi = 0; mi < 4; mi++) {
                int base = (wm + mi * 16 + g) * ROW_BYTES + kB + t4 * 4;
                af[mi][0] = *(const uint32_t*)(As + base);
                af[mi][1] = *(const uint32_t*)(As + base + 8 * ROW_BYTES);
                af[mi][2] = *(const uint32_t*)(As + base + 16);
                af[mi][3] = *(const uint32_t*)(As + base + 8 * ROW_BYTES + 16);
            }
            #pragma unroll
            for (int ni = 0; ni < 8; ni++) {
                int bb = (wn + ni * 8 + g) * ROW_BYTES + kB + t4 * 4;
                bf[ni][0] = *(const uint32_t*)(Bs + bb);
                bf[ni][1] = *(const uint32_t*)(Bs + bb + 16);
            }
            #pragma unroll
            for (int mi = 0; mi < 4; mi++)
                #pragma unroll
                for (int ni = 0; ni < 8; ni++) {
                    asm volatile(
                        "mma.sync.aligned.m16n8k16.row.col.f32.f16.f16.f32 "
                        "{%0,%1,%2,%3},{%4,%5,%6,%7},{%8,%9},{%0,%1,%2,%3};"
                        : "+f"(acc[mi][ni][0]), "+f"(acc[mi][ni][1]),
                          "+f"(acc[mi][ni][2]), "+f"(acc[mi][ni][3])
                        : "r"(af[mi][0]), "r"(af[mi][1]),
                          "r"(af[mi][2]), "r"(af[mi][3]),
                          "r"(bf[ni][0]), "r"(bf[ni][1]));
                }
        }
    };

    // ---- 3-stage ring, single sync per chunk ----
    const int T = K >> 6;
    issue(0, 0);
    if (T > 1) issue(1, 1);
    for (int i = 0; i < T; i++) {
        if (i + 2 < T) cp_wait1(); else cp_wait0();
        __syncthreads();
        if (i + 2 < T) issue((i + 2) % NSTAGE, i + 2);
        compute(i % NSTAGE);
    }

    // ---- epilogue ----
    float gate = 1.0f, gate2 = 1.0f;
    if (gate_logit)  gate  = 1.0f / (1.0f + expf(-(*gate_logit)));
    if (gate_logit2) gate2 = 1.0f / (1.0f + expf(-(*gate_logit2)));

    #pragma unroll
    for (int mi = 0; mi < 4; mi++) {
        #pragma unroll
        for (int rr = 0; rr < 2; rr++) {
            int m = m0 + wm + mi * 16 + g + rr * 8;
            if (m >= M) continue;
            long long crow = (clen > 0)
                ? (long long)(m / clen) * L_ + cstart + (m % clen)
                : (long long)m;
            #pragma unroll
            for (int ni = 0; ni < 8; ni++) {
                int n = n0 + wn + ni * 8 + t4 * 2;
                float v0 = acc[mi][ni][rr * 2 + 0];
                float v1 = acc[mi][ni][rr * 2 + 1];
                if (bias) { v0 += bias[n]; v1 += bias[n + 1]; }
                if (dualOut) {
                    float gs = (n < 1024) ? gate : gate2;
                    long long off = crow * 1024 + (n & 1023)
                                  + ((n >= 1024) ? OUT_HALF_STRIDE : 0LL);
                    float* cp = (float*)C + off;
                    cp[0] = v0 * gs; cp[1] = v1 * gs;
                } else if (outHalf) {
                    __half* cp = (__half*)C + crow * (long long)ldc + n;
                    *(__half2*)cp = __floats2half2_rn(v0 * gate, v1 * gate);
                } else {
                    float* cp = (float*)C + crow * (long long)ldc + n;
                    cp[0] = v0 * gate; cp[1] = v1 * gate;
                }
            }
        }
    }
}

// ---------------------------------------------------------------------------
__global__ void hgemm(const __half* __restrict__ A, int lda,
                      const __half* __restrict__ B, int ldb,
                      void* __restrict__ C, int ldc,
                      int M, int K,
                      const float* __restrict__ bias,
                      const float* __restrict__ gate_logit,
                      int outHalf)
{
    hcore(A, lda, B, ldb, C, ldc, M, K, 0, 0, 0, 0,
          bias, gate_logit, nullptr,
          blockIdx.y * 256, blockIdx.x * 128, outHalf != 0, false);
}

// Merged up-projection: N=2048, K=128 over zero-padded [wk2^T|0 ; 0|wv2^T].
// out[:, n<1024] = mid_k @ wk2 (gate gk); out[:, n>=1024] = mid_v @ wv2 (gate gv).
__global__ void upproj_kernel(const float* __restrict__ gk,
                              const float* __restrict__ gv,
                              float* __restrict__ out)
{
    hcore(g_mid, 128, g_w34p, 128, out, 0,
          B_ * L_, 128, 0, 0, 0, 0,
          g_b34, gk, gv,
          blockIdx.y * 256, blockIdx.x * 128, false, true);
}

// Fused scores: all 10 segments (1456 tiles). A=Q remapped; C = f32 scores.
__global__ void scores_kernel()
{
    int t = blockIdx.x;
    int seg = 0;
    #pragma unroll
    for (int i = 1; i < NSEG; i++) if (t >= c_stp[i]) seg = i;
    int local = t - c_stp[seg];
    int nt = seg + 1;
    int tm = local / nt;
    int tn = local - tm * nt;
    int len = c_len[seg], start = c_start[seg];
    int Nseg = 128 * nt, Mseg = 64 * len;
    hcore(g_Q, C_, g_KVh, 2048, g_S + c_base[seg], Nseg,
          Mseg, C_, len, start, 0, 0, nullptr, nullptr, nullptr,
          tm * 256, tn * 128, false, false);
}

// Fused attn@V: all 10 segments (1384 tiles). A = probs (half); C = MC (half).
__global__ void attnv_kernel()
{
    int t = blockIdx.x;
    int seg = 0;
    #pragma unroll
    for (int i = 1; i < NSEG; i++) if (t >= c_atp[i]) seg = i;
    int local = t - c_atp[seg];
    int tm = local >> 3;
    int tn = local & 7;
    int len = c_len[seg], start = c_start[seg];
    int Nseg = 128 * (seg + 1), Mseg = 64 * len;
    hcore(g_P + c_base[seg], Nseg, g_Vt, 1280, g_MC, C_,
          Mseg, Nseg, 0, 0, len, start, nullptr, nullptr, nullptr,
          tm * 256, tn * 128, true, false);
}

// ---------------------------------------------------------------------------
// Row softmax: single gmem read (smem row buffer), single exp, half write.
// scale = (1/32)/clip(exp(log_temp), 0.05, 1)
// ---------------------------------------------------------------------------
__global__ void softmax_kernel(const float* __restrict__ log_temp)
{
    __shared__ float buf[1280];
    __shared__ float sh[8];

    int row = blockIdx.x;
    int b = row / L_;
    int l = row - b * L_;

    int seg = 0;
    #pragma unroll
    for (int s2 = 1; s2 < NSEG; s2++)
        if (l >= c_start[s2]) seg = s2;

    const int n   = 128 * (seg + 1);
    const int len = c_len[seg];
    long long off = c_base[seg] + ((long long)b * len + (l - c_start[seg])) * (long long)n;
    const float* p = g_S + off;
    __half* q = g_P + off;

    float t = expf(*log_temp);
    t = fminf(fmaxf(t, 0.05f), 1.0f);
    const float scale = (1.0f / 32.0f) / t;

    const int lane = threadIdx.x & 31;
    const int w    = threadIdx.x >> 5;

    // pass 1: load+scale into smem, reduce max
    float m = -1e30f;
    for (int j = threadIdx.x; j < n; j += 256) {
        float v = p[j] * scale;
        buf[j] = v;
        m = fmaxf(m, v);
    }
    #pragma unroll
    for (int o = 16; o; o >>= 1) m = fmaxf(m, __shfl_xor_sync(0xffffffffu, m, o));
    if (lane == 0) sh[w] = m;
    __syncthreads();
    m = sh[lane & 7];
    #pragma unroll
    for (int o = 4; o; o >>= 1) m = fmaxf(m, __shfl_xor_sync(0xffffffffu, m, o));

    // pass 2: exp in smem, reduce sum
    float sum = 0.f;
    for (int j = threadIdx.x; j < n; j += 256) {
        float e = expf(buf[j] - m);
        buf[j] = e;
        sum += e;
    }
    #pragma unroll
    for (int o = 16; o; o >>= 1) sum += __shfl_xor_sync(0xffffffffu, sum, o);
    __syncthreads();
    if (lane == 0) sh[w] = sum;
    __syncthreads();
    sum = sh[lane & 7];
    #pragma unroll
    for (int o = 4; o; o >>= 1) sum += __shfl_xor_sync(0xffffffffu, sum, o);

    const float inv = 1.0f / sum;
    for (int j = threadIdx.x; j < n; j += 256)
        q[j] = __float2half_rn(buf[j] * inv);
}

// ---------------------------------------------------------------------------
// Utility kernels
// ---------------------------------------------------------------------------
__global__ void f2h_kernel(const float* __restrict__ src,
                           __half* __restrict__ dst, int n4)
{
    int i = blockIdx.x * 256 + threadIdx.x;
    if (i < n4) {
        float4 v = ((const float4*)src)[i];
        ((__half2*)dst)[i * 2 + 0] = __floats2half2_rn(v.x, v.y);
        ((__half2*)dst)[i * 2 + 1] = __floats2half2_rn(v.z, v.w);
    }
}

// dst[c*dld + r] = (half)src[r*sld + c]
__global__ void transpose_f2h(const float* __restrict__ src, int sld,
                              __half* __restrict__ dst, int dld,
                              int R, int Cc)
{
    __shared__ float t[32][33];
    int bx = blockIdx.x * 32, by = blockIdx.y * 32;
    int x = bx + threadIdx.x, y = by + threadIdx.y;
    if (x < Cc && y < R) t[threadIdx.y][threadIdx.x] = src[(long long)y * sld + x];
    __syncthreads();
    int xo = by + threadIdx.x, yo = bx + threadIdx.y;
    if (xo < R && yo < Cc)
        dst[(long long)yo * dld + xo] = __float2half_rn(t[threadIdx.x][threadIdx.y]);
}

// dst[c*dld + r] = src[r*sld + c] (half -> half)
__global__ void transpose_h2h(const __half* __restrict__ src, int sld,
                              __half* __restrict__ dst, int dld,
                              int R, int Cc)
{
    __shared__ __half t[32][33];
    int bx = blockIdx.x * 32, by = blockIdx.y * 32;
    int x = bx + threadIdx.x, y = by + threadIdx.y;
    if (x < Cc && y < R) t[threadIdx.y][threadIdx.x] = src[(long long)y * sld + x];
    __syncthreads();
    int xo = by + threadIdx.x, yo = bx + threadIdx.y;
    if (xo < R && yo < Cc)
        dst[(long long)yo * dld + xo] = t[threadIdx.x][threadIdx.y];
}

// Build zero-padded merged up-proj weight g_w34p [2048][128]:
//   n<1024:  k<64 -> wk2[k][n],  k>=64 -> 0
//   n>=1024: k<64 -> 0,          k>=64 -> wv2[k-64][n-1024]
__global__ void pack_w34_kernel(const float* __restrict__ wk2,
                                const float* __restrict__ wv2)
{
    int idx = blockIdx.x * 256 + threadIdx.x;   // over 2048*128
    if (idx >= 2048 * 128) return;
    int n = idx >> 7, k = idx & 127;
    float v = 0.f;
    if (n < 1024) { if (k < 64) v = wk2[k * 1024 + n]; }
    else          { if (k >= 64) v = wv2[(k - 64) * 1024 + (n - 1024)]; }
    g_w34p[idx] = __float2half_rn(v);
}

__global__ void bias_pack_kernel(const float* __restrict__ bk1,
                                 const float* __restrict__ bv1,
                                 const float* __restrict__ bk2,
                                 const float* __restrict__ bv2)
{
    int i = blockIdx.x * 256 + threadIdx.x;
    if (i < 64) { g_b12[i] = bk1[i]; g_b12[64 + i] = bv1[i]; }
    if (i < 1024) { g_b34[i] = bk2[i]; g_b34[1024 + i] = bv2[i]; }
}

__global__ void tail_kernel(float* out, long long off)
{
    if (threadIdx.x < 2) out[off + threadIdx.x] = 0.f;
}

// ---------------------------------------------------------------------------
extern "C" void kernel_launch(void* const* d_in, const int* in_sizes, int n_in,
                              void* d_out, int out_size)
{
    const float* x   = (const float*)d_in[0];
    const float* mem = (const float*)d_in[1];
    const float* Wq  = (const float*)d_in[2];
    const float* Wk  = (const float*)d_in[3];
    const float* Wv  = (const float*)d_in[4];
    const float* wk1 = (const float*)d_in[5];
    const float* bk1 = (const float*)d_in[6];
    const float* wk2 = (const float*)d_in[7];
    const float* bk2 = (const float*)d_in[8];
    const float* wv1 = (const float*)d_in[9];
    const float* bv1 = (const float*)d_in[10];
    const float* wv2 = (const float*)d_in[11];
    const float* bv2 = (const float*)d_in[12];
    const float* gk  = (const float*)d_in[13];
    const float* gv  = (const float*)d_in[14];
    const float* lt  = (const float*)d_in[15];
    float* out = (float*)d_out;

    __half *xh, *memh, *Q, *KVh, *Vt, *MC, *mid, *WqT, *wkvT, *w12T;
    float *b12;
    cudaGetSymbolAddress((void**)&xh,   g_xh);
    cudaGetSymbolAddress((void**)&memh, g_memh);
    cudaGetSymbolAddress((void**)&Q,    g_Q);
    cudaGetSymbolAddress((void**)&KVh,  g_KVh);
    cudaGetSymbolAddress((void**)&Vt,   g_Vt);
    cudaGetSymbolAddress((void**)&MC,   g_MC);
    cudaGetSymbolAddress((void**)&mid,  g_mid);
    cudaGetSymbolAddress((void**)&WqT,  g_WqT);
    cudaGetSymbolAddress((void**)&wkvT, g_wkvT);
    cudaGetSymbolAddress((void**)&w12T, g_w12T);
    cudaGetSymbolAddress((void**)&b12,  g_b12);

    cudaFuncSetAttribute(hgemm,         cudaFuncAttributeMaxDynamicSharedMemorySize, SMEM_BYTES);
    cudaFuncSetAttribute(scores_kernel, cudaFuncAttributeMaxDynamicSharedMemorySize, SMEM_BYTES);
    cudaFuncSetAttribute(attnv_kernel,  cudaFuncAttributeMaxDynamicSharedMemorySize, SMEM_BYTES);
    cudaFuncSetAttribute(upproj_kernel, cudaFuncAttributeMaxDynamicSharedMemorySize, SMEM_BYTES);

    dim3 tb(32, 32);

    // 0) convert / transpose inputs & weights to half
    f2h_kernel<<<43520, 256>>>(x,   xh,   (B_ * L_ * C_) / 4);
    f2h_kernel<<<1280,  256>>>(mem, memh, (NSEG * 128 * C_) / 4);
    transpose_f2h<<<dim3(32, 32), tb>>>(Wq,  C_, WqT,            C_, C_, C_);
    transpose_f2h<<<dim3(32, 32), tb>>>(Wk,  C_, wkvT,           C_, C_, C_);
    transpose_f2h<<<dim3(32, 32), tb>>>(Wv,  C_, wkvT + 1048576, C_, C_, C_);
    transpose_f2h<<<dim3(2,  32), tb>>>(wk1, 64, w12T,           C_, C_, 64);
    transpose_f2h<<<dim3(2,  32), tb>>>(wv1, 64, w12T + 65536,   C_, C_, 64);
    pack_w34_kernel<<<1024, 256>>>(wk2, wv2);
    bias_pack_kernel<<<4, 256>>>(bk1, bv1, bk2, bv2);

    // 1) projections: Q = x@Wq (half out); KV = mem@[Wk|Wv] (half out)
    hgemm<<<dim3(8, 170), 256, SMEM_BYTES>>>(xh,   C_, WqT,  C_, Q,   C_,
                                             B_ * L_,    C_, nullptr, nullptr, 1);
    hgemm<<<dim3(16, 5),  256, SMEM_BYTES>>>(memh, C_, wkvT, C_, KVh, 2048,
                                             NSEG * 128, C_, nullptr, nullptr, 1);

    // 1b) V^T (half): Vt[c][t] = KV[t][1024+c]
    transpose_h2h<<<dim3(32, 40), tb>>>(KVh + 1024, 2048, Vt, 1280, NSEG * 128, C_);

    // 2) all score GEMMs (f32 scores)
    scores_kernel<<<1456, 256, SMEM_BYTES>>>();

    // 3) softmax: f32 scores -> half probs (single-pass gmem)
    softmax_kernel<<<B_ * L_, 256>>>(lt);

    // 4) all attn @ V GEMMs (half MC)
    attnv_kernel<<<1384, 256, SMEM_BYTES>>>();

    // 5) mid = MC @ [wk1|wv1] + [bk1|bv1] (half out)
    hgemm<<<dim3(1, 170), 256, SMEM_BYTES>>>(MC, C_, w12T, C_, mid, 128,
                                             B_ * L_, C_, b12, nullptr, 1);

    // 6) merged up-projection (K=128, zero-padded weights): one N=2048 launch
    upproj_kernel<<<dim3(16, 170), 256, SMEM_BYTES>>>(gk, gv, out);

    // 7) trailing two scalar zeros
    tail_kernel<<<1, 32>>>(out, 2LL * B_ * L_ * C_);
}

// round 15
// speedup vs baseline: 1.4999x; 1.0409x over previous
#include <cuda_runtime.h>
#include <cuda_fp16.h>
#include <math.h>
#include <stdint.h>

// Problem constants (fixed by setup_inputs)
#define B_   64
#define L_   680
#define C_   1024
#define NSEG 10

__constant__ int       c_start[NSEG] = {0,1,5,14,30,55,91,155,255,424};
__constant__ int       c_len[NSEG]   = {1,4,9,16,25,36,64,100,169,256};
__constant__ long long c_base[NSEG]  = {0LL,8192LL,73728LL,294912LL,819200LL,
                                        1843200LL,3612672LL,7282688LL,13836288LL,26296320LL};
// Tile prefix tables for BM=256 tiles:
//   mtiles_i = ceil(64*len_i/256) = {1,1,3,4,7,9,16,25,43,64}
__constant__ int c_stp[NSEG + 1] = {0,1,3,12,28,63,117,229,429,816,1456};
__constant__ int c_atp[NSEG + 1] = {0,8,16,40,72,128,200,328,528,872,1384};

// Static device scratch
__device__ __align__(16) __half g_xh  [44564480]; // x as half
__device__ __align__(16) __half g_memh[1310720];  // mem as half
__device__ __align__(16) __half g_Q   [44564480]; // Q (half)
__device__ __align__(16) __half g_KVh [2621440];  // [1280][2048] K|V (half)
__device__ __align__(16) __half g_Vt  [1310720];  // [1024][1280] V^T (half)
__device__ __align__(16) float  g_S   [47267840]; // scores (f32, segment-packed)
__device__ __align__(16) __half g_P   [47267840]; // attn probs (half, same packing)
__device__ __align__(16) __half g_MC  [44564480]; // mem_combined (half)
__device__ __align__(16) __half g_mid [5570560];  // [43520][128] (half)
__device__ __align__(16) __half g_WqT [1048576];  // Wq^T [1024][1024]
__device__ __align__(16) __half g_wkvT[2097152];  // [2048][1024] Wk^T|Wv^T
__device__ __align__(16) __half g_w12T[131072];   // [128][1024] wk1^T|wv1^T
__device__ __align__(16) __half g_w34T[131072];   // wk2^T [1024][64] @0 | wv2^T @65536
__device__ float  g_b12 [128];                    // bk1|bv1 (f32)

// Smem: per stage, A 256 rows x 144B = 36864, B 128 rows x 144B = 18432
#define ROW_BYTES    144
#define A_STAGE_B    36864
#define B_STAGE_B    18432
#define STAGE_B      55296
#define NSTAGE       3
#define SMEM_BYTES   (NSTAGE * STAGE_B)   // 165888

__device__ __forceinline__ void cp16(uint32_t dst, const void* src, int szbytes) {
    asm volatile("cp.async.cg.shared.global [%0], [%1], 16, %2;"
                 :: "r"(dst), "l"(src), "r"(szbytes));
}
__device__ __forceinline__ void cp_commit() { asm volatile("cp.async.commit_group;"); }
__device__ __forceinline__ void cp_wait1()  { asm volatile("cp.async.wait_group 1;"); }
__device__ __forceinline__ void cp_wait0()  { asm volatile("cp.async.wait_group 0;"); }

// ---------------------------------------------------------------------------
// FP16 NT GEMM core (R11-proven): one 256x128 C-tile at (m0, n0).
//   A: [M,K] half (lda); alen>0 => row remap (m/alen)*680+astart+(m%alen)
//   B: [N,K] half (ldb); n0+128 <= N (all N multiples of 128)
//   C: [M,N]; clen>0 => row remap; half or f32 output
// K % 64 == 0. M edge zero-filled + store-guarded.
// 256 threads, 8 warps, 64x64 warp tile, m16n8k16 f16 mma, f32 accum.
// 3-stage cp.async ring, one __syncthreads per K-chunk, scalar fragment LDS.
// ---------------------------------------------------------------------------
__device__ __forceinline__ void hcore(
    const __half* __restrict__ A, int lda,
    const __half* __restrict__ B, int ldb,
    void* __restrict__ C, int ldc,
    int M, int K,
    int alen, int astart, int clen, int cstart,
    const float* __restrict__ bias,
    const float* __restrict__ gate_logit,
    int m0, int n0, bool outHalf)
{
    extern __shared__ char smraw[];
    const uint32_t smb = (uint32_t)__cvta_generic_to_shared(smraw);

    const int tid  = threadIdx.x;
    const int lane = tid & 31;
    const int w    = tid >> 5;
    const int wm   = (w & 3) * 64;
    const int wn   = (w >> 2) * 64;
    const int g    = lane >> 2;
    const int t4   = lane & 3;

    float acc[4][8][4];
    #pragma unroll
    for (int i = 0; i < 4; i++)
        #pragma unroll
        for (int j = 0; j < 8; j++)
            #pragma unroll
            for (int k = 0; k < 4; k++) acc[i][j][k] = 0.f;

    // ---- A: thread owns row m0+tid; 64 halves (128B) per chunk = 8 cp16 ----
    const int am    = m0 + tid;
    const bool amOK = am < M;
    const int amc   = amOK ? am : 0;
    long long arow = (alen > 0)
        ? (long long)(amc / alen) * L_ + astart + (amc % alen)
        : (long long)amc;
    const __half* Aptr = A + arow * (long long)lda;
    const int a_sz = amOK ? 16 : 0;
    const uint32_t a_dst = smb + (uint32_t)tid * ROW_BYTES;

    // ---- B: 128 rows; thread covers row tid>>1, half-row part (tid&1) ----
    const int brow = tid >> 1;
    const int bp   = tid & 1;
    const __half* Bptr = B + (long long)(n0 + brow) * ldb + bp * 32;
    const uint32_t b_dst = smb + A_STAGE_B + (uint32_t)brow * ROW_BYTES + (uint32_t)bp * 64u;

    auto issue = [&](int s, int chunk) {
        int k0 = chunk * 64;
        uint32_t soff = (uint32_t)s * STAGE_B;
        const __half* ap = Aptr + k0;
        uint32_t ad = a_dst + soff;
        #pragma unroll
        for (int j = 0; j < 8; j++)
            cp16(ad + j * 16, ap + j * 8, a_sz);
        const __half* bpp = Bptr + k0;
        uint32_t bd = b_dst + soff;
        #pragma unroll
        for (int j = 0; j < 4; j++)
            cp16(bd + j * 16, bpp + j * 8, 16);
        cp_commit();
    };

    auto compute = [&](int s) {
        const char* As = smraw + s * STAGE_B;
        const char* Bs = smraw + s * STAGE_B + A_STAGE_B;
        #pragma unroll
        for (int kb = 0; kb < 4; kb++) {
            const int kB = kb * 32;     // 16 halves = 32 bytes per k-step
            uint32_t af[4][4], bf[8][2];
            #pragma unroll
            for (int mi = 0; mi < 4; mi++) {
                int base = (wm + mi * 16 + g) * ROW_BYTES + kB + t4 * 4;
                af[mi][0] = *(const uint32_t*)(As + base);
                af[mi][1] = *(const uint32_t*)(As + base + 8 * ROW_BYTES);
                af[mi][2] = *(const uint32_t*)(As + base + 16);
                af[mi][3] = *(const uint32_t*)(As + base + 8 * ROW_BYTES + 16);
            }
            #pragma unroll
            for (int ni = 0; ni < 8; ni++) {
                int bb = (wn + ni * 8 + g) * ROW_BYTES + kB + t4 * 4;
                bf[ni][0] = *(const uint32_t*)(Bs + bb);
                bf[ni][1] = *(const uint32_t*)(Bs + bb + 16);
            }
            #pragma unroll
            for (int mi = 0; mi < 4; mi++)
                #pragma unroll
                for (int ni = 0; ni < 8; ni++) {
                    asm volatile(
                        "mma.sync.aligned.m16n8k16.row.col.f32.f16.f16.f32 "
                        "{%0,%1,%2,%3},{%4,%5,%6,%7},{%8,%9},{%0,%1,%2,%3};"
                        : "+f"(acc[mi][ni][0]), "+f"(acc[mi][ni][1]),
                          "+f"(acc[mi][ni][2]), "+f"(acc[mi][ni][3])
                        : "r"(af[mi][0]), "r"(af[mi][1]),
                          "r"(af[mi][2]), "r"(af[mi][3]),
                          "r"(bf[ni][0]), "r"(bf[ni][1]));
                }
        }
    };

    // ---- 3-stage ring, single sync per chunk ----
    const int T = K >> 6;
    issue(0, 0);
    if (T > 1) issue(1, 1);
    for (int i = 0; i < T; i++) {
        if (i + 2 < T) cp_wait1(); else cp_wait0();
        __syncthreads();
        if (i + 2 < T) issue((i + 2) % NSTAGE, i + 2);
        compute(i % NSTAGE);
    }

    // ---- epilogue ----
    float gate = 1.0f;
    if (gate_logit) gate = 1.0f / (1.0f + expf(-(*gate_logit)));

    #pragma unroll
    for (int mi = 0; mi < 4; mi++) {
        #pragma unroll
        for (int rr = 0; rr < 2; rr++) {
            int m = m0 + wm + mi * 16 + g + rr * 8;
            if (m >= M) continue;
            long long crow = (clen > 0)
                ? (long long)(m / clen) * L_ + cstart + (m % clen)
                : (long long)m;
            #pragma unroll
            for (int ni = 0; ni < 8; ni++) {
                int n = n0 + wn + ni * 8 + t4 * 2;
                float v0 = acc[mi][ni][rr * 2 + 0];
                float v1 = acc[mi][ni][rr * 2 + 1];
                if (bias) { v0 += bias[n]; v1 += bias[n + 1]; }
                v0 *= gate; v1 *= gate;
                if (outHalf) {
                    __half* cp = (__half*)C + crow * (long long)ldc + n;
                    *(__half2*)cp = __floats2half2_rn(v0, v1);
                } else {
                    float* cp = (float*)C + crow * (long long)ldc + n;
                    cp[0] = v0; cp[1] = v1;
                }
            }
        }
    }
}

// ---------------------------------------------------------------------------
__global__ void hgemm(const __half* __restrict__ A, int lda,
                      const __half* __restrict__ B, int ldb,
                      void* __restrict__ C, int ldc,
                      int M, int K,
                      const float* __restrict__ bias,
                      const float* __restrict__ gate_logit,
                      int outHalf)
{
    hcore(A, lda, B, ldb, C, ldc, M, K, 0, 0, 0, 0,
          bias, gate_logit,
          blockIdx.y * 256, blockIdx.x * 128, outHalf != 0);
}

// Fused projections: tiles 0..1359 -> Q = x@Wq ; tiles 1360..1439 -> KV = mem@[Wk|Wv]
__global__ void proj_kernel()
{
    int t = blockIdx.x;
    if (t < 1360) {
        int tm = t >> 3, tn = t & 7;
        hcore(g_xh, C_, g_WqT, C_, g_Q, C_, B_ * L_, C_,
              0, 0, 0, 0, nullptr, nullptr, tm * 256, tn * 128, true);
    } else {
        int local = t - 1360;
        int tm = local >> 4, tn = local & 15;
        hcore(g_memh, C_, g_wkvT, C_, g_KVh, 2048, NSEG * 128, C_,
              0, 0, 0, 0, nullptr, nullptr, tm * 256, tn * 128, true);
    }
}

// Fused scores: all 10 segments (1456 tiles). A=Q remapped; C = f32 scores.
__global__ void scores_kernel()
{
    int t = blockIdx.x;
    int seg = 0;
    #pragma unroll
    for (int i = 1; i < NSEG; i++) if (t >= c_stp[i]) seg = i;
    int local = t - c_stp[seg];
    int nt = seg + 1;
    int tm = local / nt;
    int tn = local - tm * nt;
    int len = c_len[seg], start = c_start[seg];
    int Nseg = 128 * nt, Mseg = 64 * len;
    hcore(g_Q, C_, g_KVh, 2048, g_S + c_base[seg], Nseg,
          Mseg, C_, len, start, 0, 0, nullptr, nullptr,
          tm * 256, tn * 128, false);
}

// Fused attn@V: all 10 segments (1384 tiles). A = probs (half); C = MC (half).
__global__ void attnv_kernel()
{
    int t = blockIdx.x;
    int seg = 0;
    #pragma unroll
    for (int i = 1; i < NSEG; i++) if (t >= c_atp[i]) seg = i;
    int local = t - c_atp[seg];
    int tm = local >> 3;
    int tn = local & 7;
    int len = c_len[seg], start = c_start[seg];
    int Nseg = 128 * (seg + 1), Mseg = 64 * len;
    hcore(g_P + c_base[seg], Nseg, g_Vt, 1280, g_MC, C_,
          Mseg, Nseg, 0, 0, len, start, nullptr, nullptr,
          tm * 256, tn * 128, true);
}

// ---------------------------------------------------------------------------
// Row softmax: single gmem read (smem row buffer), single exp, half write.
// scale = (1/32)/clip(exp(log_temp), 0.05, 1)
// ---------------------------------------------------------------------------
__global__ void softmax_kernel(const float* __restrict__ log_temp)
{
    __shared__ float buf[1280];
    __shared__ float sh[8];

    int row = blockIdx.x;
    int b = row / L_;
    int l = row - b * L_;

    int seg = 0;
    #pragma unroll
    for (int s2 = 1; s2 < NSEG; s2++)
        if (l >= c_start[s2]) seg = s2;

    const int n   = 128 * (seg + 1);
    const int len = c_len[seg];
    long long off = c_base[seg] + ((long long)b * len + (l - c_start[seg])) * (long long)n;
    const float* p = g_S + off;
    __half* q = g_P + off;

    float t = expf(*log_temp);
    t = fminf(fmaxf(t, 0.05f), 1.0f);
    const float scale = (1.0f / 32.0f) / t;

    const int lane = threadIdx.x & 31;
    const int w    = threadIdx.x >> 5;

    // pass 1: load+scale into smem, reduce max
    float m = -1e30f;
    for (int j = threadIdx.x; j < n; j += 256) {
        float v = p[j] * scale;
        buf[j] = v;
        m = fmaxf(m, v);
    }
    #pragma unroll
    for (int o = 16; o; o >>= 1) m = fmaxf(m, __shfl_xor_sync(0xffffffffu, m, o));
    if (lane == 0) sh[w] = m;
    __syncthreads();
    m = sh[lane & 7];
    #pragma unroll
    for (int o = 4; o; o >>= 1) m = fmaxf(m, __shfl_xor_sync(0xffffffffu, m, o));

    // pass 2: exp in smem, reduce sum
    float sum = 0.f;
    for (int j = threadIdx.x; j < n; j += 256) {
        float e = expf(buf[j] - m);
        buf[j] = e;
        sum += e;
    }
    #pragma unroll
    for (int o = 16; o; o >>= 1) sum += __shfl_xor_sync(0xffffffffu, sum, o);
    __syncthreads();
    if (lane == 0) sh[w] = sum;
    __syncthreads();
    sum = sh[lane & 7];
    #pragma unroll
    for (int o = 4; o; o >>= 1) sum += __shfl_xor_sync(0xffffffffu, sum, o);

    const float inv = 1.0f / sum;
    for (int j = threadIdx.x; j < n; j += 256)
        q[j] = __float2half_rn(buf[j] * inv);
}

// ---------------------------------------------------------------------------
// Utility kernels
// ---------------------------------------------------------------------------
__global__ void f2h_kernel(const float* __restrict__ src,
                           __half* __restrict__ dst, int n4)
{
    int i = blockIdx.x * 256 + threadIdx.x;
    if (i < n4) {
        float4 v = ((const float4*)src)[i];
        ((__half2*)dst)[i * 2 + 0] = __floats2half2_rn(v.x, v.y);
        ((__half2*)dst)[i * 2 + 1] = __floats2half2_rn(v.z, v.w);
    }
}

// dst[c*dld + r] = (half)src[r*sld + c]
__global__ void transpose_f2h(const float* __restrict__ src, int sld,
                              __half* __restrict__ dst, int dld,
                              int R, int Cc)
{
    __shared__ float t[32][33];
    int bx = blockIdx.x * 32, by = blockIdx.y * 32;
    int x = bx + threadIdx.x, y = by + threadIdx.y;
    if (x < Cc && y < R) t[threadIdx.y][threadIdx.x] = src[(long long)y * sld + x];
    __syncthreads();
    int xo = by + threadIdx.x, yo = bx + threadIdx.y;
    if (xo < R && yo < Cc)
        dst[(long long)yo * dld + xo] = __float2half_rn(t[threadIdx.x][threadIdx.y]);
}

// dst[c*dld + r] = src[r*sld + c] (half -> half)
__global__ void transpose_h2h(const __half* __restrict__ src, int sld,
                              __half* __restrict__ dst, int dld,
                              int R, int Cc)
{
    __shared__ __half t[32][33];
    int bx = blockIdx.x * 32, by = blockIdx.y * 32;
    int x = bx + threadIdx.x, y = by + threadIdx.y;
    if (x < Cc && y < R) t[threadIdx.y][threadIdx.x] = src[(long long)y * sld + x];
    __syncthreads();
    int xo = by + threadIdx.x, yo = bx + threadIdx.y;
    if (xo < R && yo < Cc)
        dst[(long long)yo * dld + xo] = t[threadIdx.x][threadIdx.y];
}

__global__ void bias_pack_kernel(const float* __restrict__ bk1,
                                 const float* __restrict__ bv1)
{
    int i = threadIdx.x;
    if (i < 64) { g_b12[i] = bk1[i]; g_b12[64 + i] = bv1[i]; }
}

__global__ void tail_kernel(float* out, long long off)
{
    if (threadIdx.x < 2) out[off + threadIdx.x] = 0.f;
}

// ---------------------------------------------------------------------------
extern "C" void kernel_launch(void* const* d_in, const int* in_sizes, int n_in,
                              void* d_out, int out_size)
{
    const float* x   = (const float*)d_in[0];
    const float* mem = (const float*)d_in[1];
    const float* Wq  = (const float*)d_in[2];
    const float* Wk  = (const float*)d_in[3];
    const float* Wv  = (const float*)d_in[4];
    const float* wk1 = (const float*)d_in[5];
    const float* bk1 = (const float*)d_in[6];
    const float* wk2 = (const float*)d_in[7];
    const float* bk2 = (const float*)d_in[8];
    const float* wv1 = (const float*)d_in[9];
    const float* bv1 = (const float*)d_in[10];
    const float* wv2 = (const float*)d_in[11];
    const float* bv2 = (const float*)d_in[12];
    const float* gk  = (const float*)d_in[13];
    const float* gv  = (const float*)d_in[14];
    const float* lt  = (const float*)d_in[15];
    float* out = (float*)d_out;

    __half *xh, *memh, *KVh, *Vt, *MC, *mid, *WqT, *wkvT, *w12T, *w34T;
    float *b12;
    cudaGetSymbolAddress((void**)&xh,   g_xh);
    cudaGetSymbolAddress((void**)&memh, g_memh);
    cudaGetSymbolAddress((void**)&KVh,  g_KVh);
    cudaGetSymbolAddress((void**)&Vt,   g_Vt);
    cudaGetSymbolAddress((void**)&MC,   g_MC);
    cudaGetSymbolAddress((void**)&mid,  g_mid);
    cudaGetSymbolAddress((void**)&WqT,  g_WqT);
    cudaGetSymbolAddress((void**)&wkvT, g_wkvT);
    cudaGetSymbolAddress((void**)&w12T, g_w12T);
    cudaGetSymbolAddress((void**)&w34T, g_w34T);
    cudaGetSymbolAddress((void**)&b12,  g_b12);

    cudaFuncSetAttribute(hgemm,         cudaFuncAttributeMaxDynamicSharedMemorySize, SMEM_BYTES);
    cudaFuncSetAttribute(proj_kernel,   cudaFuncAttributeMaxDynamicSharedMemorySize, SMEM_BYTES);
    cudaFuncSetAttribute(scores_kernel, cudaFuncAttributeMaxDynamicSharedMemorySize, SMEM_BYTES);
    cudaFuncSetAttribute(attnv_kernel,  cudaFuncAttributeMaxDynamicSharedMemorySize, SMEM_BYTES);

    dim3 tb(32, 32);

    // 0) convert / transpose inputs & weights to half
    f2h_kernel<<<43520, 256>>>(x,   xh,   (B_ * L_ * C_) / 4);
    f2h_kernel<<<1280,  256>>>(mem, memh, (NSEG * 128 * C_) / 4);
    transpose_f2h<<<dim3(32, 32), tb>>>(Wq,  C_, WqT,            C_, C_, C_);
    transpose_f2h<<<dim3(32, 32), tb>>>(Wk,  C_, wkvT,           C_, C_, C_);
    transpose_f2h<<<dim3(32, 32), tb>>>(Wv,  C_, wkvT + 1048576, C_, C_, C_);
    transpose_f2h<<<dim3(2,  32), tb>>>(wk1, 64, w12T,           C_, C_, 64);
    transpose_f2h<<<dim3(2,  32), tb>>>(wv1, 64, w12T + 65536,   C_, C_, 64);
    transpose_f2h<<<dim3(32, 2),  tb>>>(wk2, C_, w34T,           64, 64, C_);
    transpose_f2h<<<dim3(32, 2),  tb>>>(wv2, C_, w34T + 65536,   64, 64, C_);
    bias_pack_kernel<<<1, 64>>>(bk1, bv1);

    // 1) fused projections: Q = x@Wq and KV = mem@[Wk|Wv], one launch
    proj_kernel<<<1440, 256, SMEM_BYTES>>>();

    // 1b) V^T (half): Vt[c][t] = KV[t][1024+c]
    transpose_h2h<<<dim3(32, 40), tb>>>(KVh + 1024, 2048, Vt, 1280, NSEG * 128, C_);

    // 2) all score GEMMs (f32 scores)
    scores_kernel<<<1456, 256, SMEM_BYTES>>>();

    // 3) softmax: f32 scores -> half probs (single gmem pass)
    softmax_kernel<<<B_ * L_, 256>>>(lt);

    // 4) all attn @ V GEMMs (half MC)
    attnv_kernel<<<1384, 256, SMEM_BYTES>>>();

    // 5) mid = MC @ [wk1|wv1] + [bk1|bv1] (half out)
    hgemm<<<dim3(1, 170), 256, SMEM_BYTES>>>(MC, C_, w12T, C_, mid, 128,
                                             B_ * L_, C_, b12, nullptr, 1);

    // 6) up-projections with bias+gate epilogue (f32 final outputs)
    hgemm<<<dim3(8, 170), 256, SMEM_BYTES>>>(mid,      128, w34T,         64,
                                             out, C_, B_ * L_, 64, bk2, gk, 0);
    hgemm<<<dim3(8, 170), 256, SMEM_BYTES>>>(mid + 64, 128, w34T + 65536, 64,
                                             out + (long long)B_ * L_ * C_, C_,
                                             B_ * L_, 64, bv2, gv, 0);

    // 7) trailing two scalar zeros
    tail_kernel<<<1, 32>>>(out, 2LL * B_ * L_ * C_);
}

// round 16
// speedup vs baseline: 1.5139x; 1.0093x over previous
#include <cuda_runtime.h>
#include <cuda_fp16.h>
#include <math.h>
#include <stdint.h>

// Problem constants (fixed by setup_inputs)
#define B_   64
#define L_   680
#define C_   1024
#define NSEG 10

__constant__ int       c_start[NSEG] = {0,1,5,14,30,55,91,155,255,424};
__constant__ int       c_len[NSEG]   = {1,4,9,16,25,36,64,100,169,256};
__constant__ long long c_base[NSEG]  = {0LL,8192LL,73728LL,294912LL,819200LL,
                                        1843200LL,3612672LL,7282688LL,13836288LL,26296320LL};
// Tile prefix tables for BM=256 tiles:
//   mtiles_i = ceil(64*len_i/256) = {1,1,3,4,7,9,16,25,43,64}
__constant__ int c_stp[NSEG + 1] = {0,1,3,12,28,63,117,229,429,816,1456};
__constant__ int c_atp[NSEG + 1] = {0,8,16,40,72,128,200,328,528,872,1384};

// Static device scratch
__device__ __align__(16) __half g_xh  [44564480]; // x as half
__device__ __align__(16) __half g_memh[1310720];  // mem as half
__device__ __align__(16) __half g_Q   [44564480]; // Q (half)
__device__ __align__(16) __half g_Kh  [1310720];  // [1280][1024] K (half)
__device__ __align__(16) __half g_Vt  [1310720];  // [1024][1280] V^T (half)
__device__ __align__(16) float  g_S   [47267840]; // scores (f32, segment-packed)
__device__ __align__(16) __half g_P   [47267840]; // attn probs (half, same packing)
__device__ __align__(16) __half g_MC  [44564480]; // mem_combined (half)
__device__ __align__(16) __half g_mid [5570560];  // [43520][128] (half)
__device__ __align__(16) __half g_WqT [1048576];  // Wq^T [1024][1024]
__device__ __align__(16) __half g_wkvT[2097152];  // [2048][1024] Wk^T|Wv^T
__device__ __align__(16) __half g_w12T[131072];   // [128][1024] wk1^T|wv1^T
__device__ __align__(16) __half g_w34T[131072];   // wk2^T [1024][64] @0 | wv2^T @65536
__device__ float  g_b12 [128];                    // bk1|bv1 (f32)

// Smem: per stage, A 256 rows x 144B = 36864, B 128 rows x 144B = 18432
#define ROW_BYTES    144
#define A_STAGE_B    36864
#define B_STAGE_B    18432
#define STAGE_B      55296
#define NSTAGE       3
#define SMEM_BYTES   (NSTAGE * STAGE_B)   // 165888

__device__ __forceinline__ void cp16(uint32_t dst, const void* src, int szbytes) {
    asm volatile("cp.async.cg.shared.global [%0], [%1], 16, %2;"
                 :: "r"(dst), "l"(src), "r"(szbytes));
}
__device__ __forceinline__ void cp_commit() { asm volatile("cp.async.commit_group;"); }
__device__ __forceinline__ void cp_wait1()  { asm volatile("cp.async.wait_group 1;"); }
__device__ __forceinline__ void cp_wait0()  { asm volatile("cp.async.wait_group 0;"); }

// ---------------------------------------------------------------------------
// FP16 NT GEMM core (R11-proven): one 256x128 C-tile at (m0, n0).
//   A: [M,K] half (lda); alen>0 => row remap (m/alen)*680+astart+(m%alen)
//   B: [N,K] half (ldb); n0+128 <= N (all N multiples of 128)
//   C: [M,N]; clen>0 => row remap; half or f32 output
// K % 64 == 0. M edge zero-filled + store-guarded.
// 256 threads, 8 warps, 64x64 warp tile, m16n8k16 f16 mma, f32 accum.
// 3-stage cp.async ring, one __syncthreads per K-chunk, scalar fragment LDS.
// ---------------------------------------------------------------------------
__device__ __forceinline__ void hcore(
    const __half* __restrict__ A, int lda,
    const __half* __restrict__ B, int ldb,
    void* __restrict__ C, int ldc,
    int M, int K,
    int alen, int astart, int clen, int cstart,
    const float* __restrict__ bias,
    const float* __restrict__ gate_logit,
    int m0, int n0, bool outHalf)
{
    extern __shared__ char smraw[];
    const uint32_t smb = (uint32_t)__cvta_generic_to_shared(smraw);

    const int tid  = threadIdx.x;
    const int lane = tid & 31;
    const int w    = tid >> 5;
    const int wm   = (w & 3) * 64;
    const int wn   = (w >> 2) * 64;
    const int g    = lane >> 2;
    const int t4   = lane & 3;

    float acc[4][8][4];
    #pragma unroll
    for (int i = 0; i < 4; i++)
        #pragma unroll
        for (int j = 0; j < 8; j++)
            #pragma unroll
            for (int k = 0; k < 4; k++) acc[i][j][k] = 0.f;

    // ---- A: thread owns row m0+tid; 64 halves (128B) per chunk = 8 cp16 ----
    const int am    = m0 + tid;
    const bool amOK = am < M;
    const int amc   = amOK ? am : 0;
    long long arow = (alen > 0)
        ? (long long)(amc / alen) * L_ + astart + (amc % alen)
        : (long long)amc;
    const __half* Aptr = A + arow * (long long)lda;
    const int a_sz = amOK ? 16 : 0;
    const uint32_t a_dst = smb + (uint32_t)tid * ROW_BYTES;

    // ---- B: 128 rows; thread covers row tid>>1, half-row part (tid&1) ----
    const int brow = tid >> 1;
    const int bp   = tid & 1;
    const __half* Bptr = B + (long long)(n0 + brow) * ldb + bp * 32;
    const uint32_t b_dst = smb + A_STAGE_B + (uint32_t)brow * ROW_BYTES + (uint32_t)bp * 64u;

    auto issue = [&](int s, int chunk) {
        int k0 = chunk * 64;
        uint32_t soff = (uint32_t)s * STAGE_B;
        const __half* ap = Aptr + k0;
        uint32_t ad = a_dst + soff;
        #pragma unroll
        for (int j = 0; j < 8; j++)
            cp16(ad + j * 16, ap + j * 8, a_sz);
        const __half* bpp = Bptr + k0;
        uint32_t bd = b_dst + soff;
        #pragma unroll
        for (int j = 0; j < 4; j++)
            cp16(bd + j * 16, bpp + j * 8, 16);
        cp_commit();
    };

    auto compute = [&](int s) {
        const char* As = smraw + s * STAGE_B;
        const char* Bs = smraw + s * STAGE_B + A_STAGE_B;
        #pragma unroll
        for (int kb = 0; kb < 4; kb++) {
            const int kB = kb * 32;     // 16 halves = 32 bytes per k-step
            uint32_t af[4][4], bf[8][2];
            #pragma unroll
            for (int mi = 0; mi < 4; mi++) {
                int base = (wm + mi * 16 + g) * ROW_BYTES + kB + t4 * 4;
                af[mi][0] = *(const uint32_t*)(As + base);
                af[mi][1] = *(const uint32_t*)(As + base + 8 * ROW_BYTES);
                af[mi][2] = *(const uint32_t*)(As + base + 16);
                af[mi][3] = *(const uint32_t*)(As + base + 8 * ROW_BYTES + 16);
            }
            #pragma unroll
            for (int ni = 0; ni < 8; ni++) {
                int bb = (wn + ni * 8 + g) * ROW_BYTES + kB + t4 * 4;
                bf[ni][0] = *(const uint32_t*)(Bs + bb);
                bf[ni][1] = *(const uint32_t*)(Bs + bb + 16);
            }
            #pragma unroll
            for (int mi = 0; mi < 4; mi++)
                #pragma unroll
                for (int ni = 0; ni < 8; ni++) {
                    asm volatile(
                        "mma.sync.aligned.m16n8k16.row.col.f32.f16.f16.f32 "
                        "{%0,%1,%2,%3},{%4,%5,%6,%7},{%8,%9},{%0,%1,%2,%3};"
                        : "+f"(acc[mi][ni][0]), "+f"(acc[mi][ni][1]),
                          "+f"(acc[mi][ni][2]), "+f"(acc[mi][ni][3])
                        : "r"(af[mi][0]), "r"(af[mi][1]),
                          "r"(af[mi][2]), "r"(af[mi][3]),
                          "r"(bf[ni][0]), "r"(bf[ni][1]));
                }
        }
    };

    // ---- 3-stage ring, single sync per chunk ----
    const int T = K >> 6;
    issue(0, 0);
    if (T > 1) issue(1, 1);
    for (int i = 0; i < T; i++) {
        if (i + 2 < T) cp_wait1(); else cp_wait0();
        __syncthreads();
        if (i + 2 < T) issue((i + 2) % NSTAGE, i + 2);
        compute(i % NSTAGE);
    }

    // ---- epilogue ----
    float gate = 1.0f;
    if (gate_logit) gate = 1.0f / (1.0f + expf(-(*gate_logit)));

    #pragma unroll
    for (int mi = 0; mi < 4; mi++) {
        #pragma unroll
        for (int rr = 0; rr < 2; rr++) {
            int m = m0 + wm + mi * 16 + g + rr * 8;
            if (m >= M) continue;
            long long crow = (clen > 0)
                ? (long long)(m / clen) * L_ + cstart + (m % clen)
                : (long long)m;
            #pragma unroll
            for (int ni = 0; ni < 8; ni++) {
                int n = n0 + wn + ni * 8 + t4 * 2;
                float v0 = acc[mi][ni][rr * 2 + 0];
                float v1 = acc[mi][ni][rr * 2 + 1];
                if (bias) { v0 += bias[n]; v1 += bias[n + 1]; }
                v0 *= gate; v1 *= gate;
                if (outHalf) {
                    __half* cp = (__half*)C + crow * (long long)ldc + n;
                    *(__half2*)cp = __floats2half2_rn(v0, v1);
                } else {
                    float* cp = (float*)C + crow * (long long)ldc + n;
                    cp[0] = v0; cp[1] = v1;
                }
            }
        }
    }
}

// ---------------------------------------------------------------------------
__global__ void hgemm(const __half* __restrict__ A, int lda,
                      const __half* __restrict__ B, int ldb,
                      void* __restrict__ C, int ldc,
                      int M, int K,
                      const float* __restrict__ bias,
                      const float* __restrict__ gate_logit,
                      int outHalf)
{
    hcore(A, lda, B, ldb, C, ldc, M, K, 0, 0, 0, 0,
          bias, gate_logit,
          blockIdx.y * 256, blockIdx.x * 128, outHalf != 0);
}

// Fused projections:
//   tiles 0..1359:    Q  = x @ Wq            (170 m x 8 n)
//   tiles 1360..1399: K  = mem @ Wk          (5 m x 8 n)
//   tiles 1400..1439: Vt = Wv^T "@" mem^T    (A=WvT, B=memh; 4 m x 10 n)
__global__ void proj_kernel()
{
    int t = blockIdx.x;
    if (t < 1360) {
        int tm = t >> 3, tn = t & 7;
        hcore(g_xh, C_, g_WqT, C_, g_Q, C_, B_ * L_, C_,
              0, 0, 0, 0, nullptr, nullptr, tm * 256, tn * 128, true);
    } else if (t < 1400) {
        int local = t - 1360;
        int tm = local >> 3, tn = local & 7;
        hcore(g_memh, C_, g_wkvT, C_, g_Kh, C_, NSEG * 128, C_,
              0, 0, 0, 0, nullptr, nullptr, tm * 256, tn * 128, true);
    } else {
        int local = t - 1400;
        int tm = local / 10, tn = local % 10;
        hcore(g_wkvT + 1048576, C_, g_memh, C_, g_Vt, 1280, 1024, C_,
              0, 0, 0, 0, nullptr, nullptr, tm * 256, tn * 128, true);
    }
}

// Fused scores: all 10 segments (1456 tiles). A=Q remapped; C = f32 scores.
__global__ void scores_kernel()
{
    int t = blockIdx.x;
    int seg = 0;
    #pragma unroll
    for (int i = 1; i < NSEG; i++) if (t >= c_stp[i]) seg = i;
    int local = t - c_stp[seg];
    int nt = seg + 1;
    int tm = local / nt;
    int tn = local - tm * nt;
    int len = c_len[seg], start = c_start[seg];
    int Nseg = 128 * nt, Mseg = 64 * len;
    hcore(g_Q, C_, g_Kh, C_, g_S + c_base[seg], Nseg,
          Mseg, C_, len, start, 0, 0, nullptr, nullptr,
          tm * 256, tn * 128, false);
}

// Fused attn@V: all 10 segments (1384 tiles). A = probs (half); C = MC (half).
__global__ void attnv_kernel()
{
    int t = blockIdx.x;
    int seg = 0;
    #pragma unroll
    for (int i = 1; i < NSEG; i++) if (t >= c_atp[i]) seg = i;
    int local = t - c_atp[seg];
    int tm = local >> 3;
    int tn = local & 7;
    int len = c_len[seg], start = c_start[seg];
    int Nseg = 128 * (seg + 1), Mseg = 64 * len;
    hcore(g_P + c_base[seg], Nseg, g_Vt, 1280, g_MC, C_,
          Mseg, Nseg, 0, 0, len, start, nullptr, nullptr,
          tm * 256, tn * 128, true);
}

// ---------------------------------------------------------------------------
// Row softmax: single gmem read (smem row buffer), single exp, half write.
// scale = (1/32)/clip(exp(log_temp), 0.05, 1)
// ---------------------------------------------------------------------------
__global__ void softmax_kernel(const float* __restrict__ log_temp)
{
    __shared__ float buf[1280];
    __shared__ float sh[8];

    int row = blockIdx.x;
    int b = row / L_;
    int l = row - b * L_;

    int seg = 0;
    #pragma unroll
    for (int s2 = 1; s2 < NSEG; s2++)
        if (l >= c_start[s2]) seg = s2;

    const int n   = 128 * (seg + 1);
    const int len = c_len[seg];
    long long off = c_base[seg] + ((long long)b * len + (l - c_start[seg])) * (long long)n;
    const float* p = g_S + off;
    __half* q = g_P + off;

    float t = expf(*log_temp);
    t = fminf(fmaxf(t, 0.05f), 1.0f);
    const float scale = (1.0f / 32.0f) / t;

    const int lane = threadIdx.x & 31;
    const int w    = threadIdx.x >> 5;

    float m = -1e30f;
    for (int j = threadIdx.x; j < n; j += 256) {
        float v = p[j] * scale;
        buf[j] = v;
        m = fmaxf(m, v);
    }
    #pragma unroll
    for (int o = 16; o; o >>= 1) m = fmaxf(m, __shfl_xor_sync(0xffffffffu, m, o));
    if (lane == 0) sh[w] = m;
    __syncthreads();
    m = sh[lane & 7];
    #pragma unroll
    for (int o = 4; o; o >>= 1) m = fmaxf(m, __shfl_xor_sync(0xffffffffu, m, o));

    float sum = 0.f;
    for (int j = threadIdx.x; j < n; j += 256) {
        float e = expf(buf[j] - m);
        buf[j] = e;
        sum += e;
    }
    #pragma unroll
    for (int o = 16; o; o >>= 1) sum += __shfl_xor_sync(0xffffffffu, sum, o);
    __syncthreads();
    if (lane == 0) sh[w] = sum;
    __syncthreads();
    sum = sh[lane & 7];
    #pragma unroll
    for (int o = 4; o; o >>= 1) sum += __shfl_xor_sync(0xffffffffu, sum, o);

    const float inv = 1.0f / sum;
    for (int j = threadIdx.x; j < n; j += 256)
        q[j] = __float2half_rn(buf[j] * inv);
}

// ---------------------------------------------------------------------------
// Fused prologue: f2h of x and mem in one launch
// ---------------------------------------------------------------------------
__global__ void f2h_all(const float* __restrict__ x, const float* __restrict__ mem)
{
    int bid = blockIdx.x;
    if (bid < 43520) {
        int i = bid * 256 + threadIdx.x;            // over 11141120 float4s
        float4 v = ((const float4*)x)[i];
        ((__half2*)g_xh)[i * 2 + 0] = __floats2half2_rn(v.x, v.y);
        ((__half2*)g_xh)[i * 2 + 1] = __floats2half2_rn(v.z, v.w);
    } else {
        int i = (bid - 43520) * 256 + threadIdx.x;  // over 327680 float4s
        float4 v = ((const float4*)mem)[i];
        ((__half2*)g_memh)[i * 2 + 0] = __floats2half2_rn(v.x, v.y);
        ((__half2*)g_memh)[i * 2 + 1] = __floats2half2_rn(v.z, v.w);
    }
}

// Fused weight pack: all 7 transposes + bias pack in one launch (3329 blocks).
__global__ void pack_weights(const float* __restrict__ Wq,
                             const float* __restrict__ Wk,
                             const float* __restrict__ Wv,
                             const float* __restrict__ wk1,
                             const float* __restrict__ wv1,
                             const float* __restrict__ wk2,
                             const float* __restrict__ wv2,
                             const float* __restrict__ bk1,
                             const float* __restrict__ bv1)
{
    int bid = blockIdx.x;
    if (bid == 3328) {
        int i = threadIdx.x;
        if (i < 64) { g_b12[i] = bk1[i]; g_b12[64 + i] = bv1[i]; }
        return;
    }
    const float* src; __half* dst;
    int sld, dld, R, Cc, base;
    if      (bid < 1024) { src = Wq;  dst = g_WqT;            sld = 1024; dld = 1024; R = 1024; Cc = 1024; base = 0; }
    else if (bid < 2048) { src = Wk;  dst = g_wkvT;           sld = 1024; dld = 1024; R = 1024; Cc = 1024; base = 1024; }
    else if (bid < 3072) { src = Wv;  dst = g_wkvT + 1048576; sld = 1024; dld = 1024; R = 1024; Cc = 1024; base = 2048; }
    else if (bid < 3136) { src = wk1; dst = g_w12T;           sld = 64;   dld = 1024; R = 1024; Cc = 64;   base = 3072; }
    else if (bid < 3200) { src = wv1; dst = g_w12T + 65536;   sld = 64;   dld = 1024; R = 1024; Cc = 64;   base = 3136; }
    else if (bid < 3264) { src = wk2; dst = g_w34T;           sld = 1024; dld = 64;   R = 64;   Cc = 1024; base = 3200; }
    else                 { src = wv2; dst = g_w34T + 65536;   sld = 1024; dld = 64;   R = 64;   Cc = 1024; base = 3264; }
    int local = bid - base;
    int tiles_x = (Cc + 31) >> 5;
    int tx = local % tiles_x, ty = local / tiles_x;

    __shared__ float tbuf[32][33];
    int thx = threadIdx.x & 31, thy = threadIdx.x >> 5;
    int xx = tx * 32 + thx, yy = ty * 32 + thy;
    if (xx < Cc && yy < R) tbuf[thy][thx] = src[(long long)yy * sld + xx];
    __syncthreads();
    int xo = ty * 32 + thx, yo = tx * 32 + thy;
    if (xo < R && yo < Cc)
        dst[(long long)yo * dld + xo] = __float2half_rn(tbuf[thx][thy]);
}

__global__ void tail_kernel(float* out, long long off)
{
    if (threadIdx.x < 2) out[off + threadIdx.x] = 0.f;
}

// ---------------------------------------------------------------------------
extern "C" void kernel_launch(void* const* d_in, const int* in_sizes, int n_in,
                              void* d_out, int out_size)
{
    const float* x   = (const float*)d_in[0];
    const float* mem = (const float*)d_in[1];
    const float* Wq  = (const float*)d_in[2];
    const float* Wk  = (const float*)d_in[3];
    const float* Wv  = (const float*)d_in[4];
    const float* wk1 = (const float*)d_in[5];
    const float* bk1 = (const float*)d_in[6];
    const float* wk2 = (const float*)d_in[7];
    const float* bk2 = (const float*)d_in[8];
    const float* wv1 = (const float*)d_in[9];
    const float* bv1 = (const float*)d_in[10];
    const float* wv2 = (const float*)d_in[11];
    const float* bv2 = (const float*)d_in[12];
    const float* gk  = (const float*)d_in[13];
    const float* gv  = (const float*)d_in[14];
    const float* lt  = (const float*)d_in[15];
    float* out = (float*)d_out;

    __half *MC, *mid, *w12T, *w34T;
    float *b12;
    cudaGetSymbolAddress((void**)&MC,   g_MC);
    cudaGetSymbolAddress((void**)&mid,  g_mid);
    cudaGetSymbolAddress((void**)&w12T, g_w12T);
    cudaGetSymbolAddress((void**)&w34T, g_w34T);
    cudaGetSymbolAddress((void**)&b12,  g_b12);

    cudaFuncSetAttribute(hgemm,         cudaFuncAttributeMaxDynamicSharedMemorySize, SMEM_BYTES);
    cudaFuncSetAttribute(proj_kernel,   cudaFuncAttributeMaxDynamicSharedMemorySize, SMEM_BYTES);
    cudaFuncSetAttribute(scores_kernel, cudaFuncAttributeMaxDynamicSharedMemorySize, SMEM_BYTES);
    cudaFuncSetAttribute(attnv_kernel,  cudaFuncAttributeMaxDynamicSharedMemorySize, SMEM_BYTES);

    // 0) fused prologue: converts + weight packs (2 launches)
    f2h_all<<<44800, 256>>>(x, mem);
    pack_weights<<<3329, 1024>>>(Wq, Wk, Wv, wk1, wv1, wk2, wv2, bk1, bv1);

    // 1) fused projections: Q, K, and V^T in one launch
    proj_kernel<<<1440, 256, SMEM_BYTES>>>();

    // 2) all score GEMMs (f32 scores)
    scores_kernel<<<1456, 256, SMEM_BYTES>>>();

    // 3) softmax: f32 scores -> half probs (single gmem pass)
    softmax_kernel<<<B_ * L_, 256>>>(lt);

    // 4) all attn @ V GEMMs (half MC)
    attnv_kernel<<<1384, 256, SMEM_BYTES>>>();

    // 5) mid = MC @ [wk1|wv1] + [bk1|bv1] (half out)
    hgemm<<<dim3(1, 170), 256, SMEM_BYTES>>>(MC, C_, w12T, C_, mid, 128,
                                             B_ * L_, C_, b12, nullptr, 1);

    // 6) up-projections with bias+gate epilogue (f32 final outputs)
    hgemm<<<dim3(8, 170), 256, SMEM_BYTES>>>(mid,      128, w34T,         64,
                                             out, C_, B_ * L_, 64, bk2, gk, 0);
    hgemm<<<dim3(8, 170), 256, SMEM_BYTES>>>(mid + 64, 128, w34T + 65536, 64,
                                             out + (long long)B_ * L_ * C_, C_,
                                             B_ * L_, 64, bv2, gv, 0);

    // 7) trailing two scalar zeros
    tail_kernel<<<1, 32>>>(out, 2LL * B_ * L_ * C_);
}